// round 3
// baseline (speedup 1.0000x reference)
#include <cuda_runtime.h>
#include <cuda_bf16.h>

// Greedy masked-argmax scan: B rows, S=25 steps, V=25 vocab.
// One warp per row, lane v owns vocab item v. Per step:
//   key = order-preserving uint32 of score (0 if used / lane>=V)
//   m = warp reduce_max(key); winner = lowest lane with key==m (ffs of ballot)
// Tie-break (exact float equality) -> lowest index, matching jnp.argmax.
//
// Output layout: float[2*B*S]; [0, B*S) = actions as float, [B*S, 2*B*S) = scores.

#define ROWS_PER_BLOCK 8
#define NTHREADS 256
#define S_LEN 25
#define V_LEN 25
#define ROW_ELEMS (S_LEN * V_LEN)  // 625

__global__ __launch_bounds__(NTHREADS)
void greedy_argmax_kernel(const float* __restrict__ in, float* __restrict__ out, int B) {
    __shared__ float tile[ROWS_PER_BLOCK * ROW_ELEMS];           // 20000 B
    __shared__ int   s_act[ROWS_PER_BLOCK][S_LEN];
    __shared__ float s_val[ROWS_PER_BLOCK][S_LEN];

    const int tid = threadIdx.x;
    const long long base = (long long)blockIdx.x * (ROWS_PER_BLOCK * ROW_ELEMS);
    const long long total = (long long)B * ROW_ELEMS;

    // ---- Stage 8 rows (5000 floats, 16B-aligned region) into smem, coalesced ----
    const long long remaining = total - base;                    // > 0 by grid sizing
    if (remaining >= ROWS_PER_BLOCK * ROW_ELEMS) {
        const float4* g4 = reinterpret_cast<const float4*>(in + base);
        float4* t4 = reinterpret_cast<float4*>(tile);
        #pragma unroll
        for (int i = 0; i < (ROWS_PER_BLOCK * ROW_ELEMS / 4); i += NTHREADS) {
            int idx = i + tid;
            if (idx < ROWS_PER_BLOCK * ROW_ELEMS / 4) t4[idx] = g4[idx];
        }
    } else {
        // tail block (B not multiple of 8): scalar guarded loads
        for (int i = tid; i < ROWS_PER_BLOCK * ROW_ELEMS; i += NTHREADS) {
            tile[i] = (i < remaining) ? in[base + i] : 0.0f;
        }
    }
    __syncthreads();

    const int w    = tid >> 5;
    const int lane = tid & 31;
    const long long row = (long long)blockIdx.x * ROWS_PER_BLOCK + w;
    const bool row_valid = (row < B);

    // ---- Preload this lane's per-step scores into registers ----
    float sc[S_LEN];
    #pragma unroll
    for (int s = 0; s < S_LEN; s++) {
        sc[s] = (lane < V_LEN) ? tile[w * ROW_ELEMS + s * V_LEN + lane] : 0.0f;
    }

    // ---- Greedy scan: 25 sequential warp-argmaxes ----
    bool used = false;
    #pragma unroll
    for (int s = 0; s < S_LEN; s++) {
        unsigned key = 0u;
        if (lane < V_LEN && !used) {
            unsigned b = __float_as_uint(sc[s]);
            // monotone float->uint: negatives -> ~b, non-negatives -> b | signbit
            key = (b & 0x80000000u) ? ~b : (b | 0x80000000u);
        }
        unsigned m = __reduce_max_sync(0xFFFFFFFFu, key);
        unsigned win = __ballot_sync(0xFFFFFFFFu, (key == m) && (m != 0u));
        int sel = __ffs(win) - 1;   // lowest lane among ties == first-occurrence argmax
        if (lane == sel) {
            used = true;
            s_act[w][s] = sel;
            s_val[w][s] = sc[s];
        }
    }
    __syncwarp();

    // ---- Coalesced writeback: actions (as float) then scores ----
    if (row_valid && lane < S_LEN) {
        const long long nBS = (long long)B * S_LEN;
        out[row * S_LEN + lane]       = (float)s_act[w][lane];
        out[nBS + row * S_LEN + lane] = s_val[w][lane];
    }
}

extern "C" void kernel_launch(void* const* d_in, const int* in_sizes, int n_in,
                              void* d_out, int out_size) {
    const float* in = (const float*)d_in[0];
    float* out = (float*)d_out;
    int B = in_sizes[0] / ROW_ELEMS;   // 65536 for the bench shape
    int blocks = (B + ROWS_PER_BLOCK - 1) / ROWS_PER_BLOCK;
    greedy_argmax_kernel<<<blocks, NTHREADS>>>(in, out, B);
}